// round 15
// baseline (speedup 1.0000x reference)
#include <cuda_runtime.h>
#include <cuda_bf16.h>
#include <math_constants.h>

#define NTOK 4096
#define CDIM 128
#define BATCH 4
#define KT 32
#define NKT (NTOK / KT)
#define SROW 264   // smem row stride in bf16 elems (256 + 8 pad -> 528B, conflict-free ldmatrix)

// scratch
__device__ float g_Q[BATCH * CDIM * NTOK];                        // fp32 [b][c][n] (input to K proj)
__device__ __nv_bfloat16 g_Qs[(size_t)BATCH * NTOK * 256];        // [b][n][ qh(128) | ql(128) ], pre-scaled
__device__ __nv_bfloat16 g_Ks[(size_t)BATCH * NTOK * 256];        // [b][m][ kh(128) | kl(128) ]

__device__ __forceinline__ unsigned smem_u32(const void* p) {
    return (unsigned)__cvta_generic_to_shared(p);
}

__device__ __forceinline__ void mma16816(float* d, const unsigned* a, unsigned b0, unsigned b1) {
    asm volatile("mma.sync.aligned.m16n8k16.row.col.f32.bf16.bf16.f32 "
                 "{%0,%1,%2,%3}, {%4,%5,%6,%7}, {%8,%9}, {%0,%1,%2,%3};"
                 : "+f"(d[0]), "+f"(d[1]), "+f"(d[2]), "+f"(d[3])
                 : "r"(a[0]), "r"(a[1]), "r"(a[2]), "r"(a[3]), "r"(b0), "r"(b1));
}

// -----------------------------------------------------------------------------
// Projection: fin[b][c][n] = sum_k in[b][k][n] * W[c][k] + bias[c]
// Writes optional fp32 [b][c][n] and always the scaled bf16 hi/lo split [b][n][2c].
// grid (64, BATCH), 256 threads; per-thread tile: 8 c x 4 n.
// -----------------------------------------------------------------------------
__global__ __launch_bounds__(256) void proj_kernel(
    const float* __restrict__ in, const float* __restrict__ W,
    const float* __restrict__ bias, float* __restrict__ out_f32,
    __nv_bfloat16* __restrict__ out_split, float scale)
{
    __shared__ float Ins[32][64];
    __shared__ float Ws[32][132];

    const int b  = blockIdx.y;
    const int n0 = blockIdx.x * 64;
    const int tid = threadIdx.x;
    const int tx = tid & 15;
    const int ty = tid >> 4;

    const float* inb = in + (size_t)b * CDIM * NTOK;

    float acc[2][4][4];
    #pragma unroll
    for (int jh = 0; jh < 2; jh++)
        #pragma unroll
        for (int jj = 0; jj < 4; jj++)
            #pragma unroll
            for (int i = 0; i < 4; i++) acc[jh][jj][i] = 0.f;

    for (int k0 = 0; k0 < CDIM; k0 += 32) {
        #pragma unroll
        for (int r = 0; r < 2; r++) {
            int idx = tid + r * 256;
            int kk = idx >> 4;
            int nn = (idx & 15) << 2;
            float4 v = *(const float4*)(inb + (size_t)(k0 + kk) * NTOK + n0 + nn);
            *(float4*)(&Ins[kk][nn]) = v;
        }
        #pragma unroll
        for (int r = 0; r < 4; r++) {
            int idx = tid + r * 256;
            int c  = idx >> 3;
            int kk = (idx & 7) << 2;
            float4 v = *(const float4*)(W + (size_t)c * CDIM + k0 + kk);
            Ws[kk + 0][c] = v.x;
            Ws[kk + 1][c] = v.y;
            Ws[kk + 2][c] = v.z;
            Ws[kk + 3][c] = v.w;
        }
        __syncthreads();

        #pragma unroll
        for (int k = 0; k < 32; k++) {
            float4 q  = *(const float4*)(&Ins[k][ty * 4]);
            float4 w0 = *(const float4*)(&Ws[k][tx * 4]);
            float4 w1 = *(const float4*)(&Ws[k][64 + tx * 4]);
            float qv[4]  = {q.x, q.y, q.z, q.w};
            float w0v[4] = {w0.x, w0.y, w0.z, w0.w};
            float w1v[4] = {w1.x, w1.y, w1.z, w1.w};
            #pragma unroll
            for (int jj = 0; jj < 4; jj++)
                #pragma unroll
                for (int i = 0; i < 4; i++) {
                    acc[0][jj][i] = fmaf(w0v[jj], qv[i], acc[0][jj][i]);
                    acc[1][jj][i] = fmaf(w1v[jj], qv[i], acc[1][jj][i]);
                }
        }
        __syncthreads();
    }

    // add bias
    float fin[2][4][4];
    #pragma unroll
    for (int jh = 0; jh < 2; jh++)
        #pragma unroll
        for (int jj = 0; jj < 4; jj++) {
            float bv = bias[jh * 64 + tx * 4 + jj];
            #pragma unroll
            for (int i = 0; i < 4; i++) fin[jh][jj][i] = acc[jh][jj][i] + bv;
        }

    if (out_f32) {
        float* outb = out_f32 + (size_t)b * CDIM * NTOK;
        #pragma unroll
        for (int jh = 0; jh < 2; jh++)
            #pragma unroll
            for (int jj = 0; jj < 4; jj++) {
                int c = jh * 64 + tx * 4 + jj;
                float4 v = make_float4(fin[jh][jj][0], fin[jh][jj][1],
                                       fin[jh][jj][2], fin[jh][jj][3]);
                *(float4*)(outb + (size_t)c * NTOK + n0 + ty * 4) = v;
            }
    }

    // scaled bf16 hi/lo split, layout [b][n][ hi(0..127) | lo(128..255) ]
    __nv_bfloat16* sb = out_split + (size_t)b * NTOK * 256;
    #pragma unroll
    for (int i = 0; i < 4; i++) {
        int n = n0 + ty * 4 + i;
        #pragma unroll
        for (int jh = 0; jh < 2; jh++) {
            __nv_bfloat16 h[4], l[4];
            #pragma unroll
            for (int jj = 0; jj < 4; jj++) {
                float v = fin[jh][jj][i] * scale;
                h[jj] = __float2bfloat16(v);
                l[jj] = __float2bfloat16(v - __bfloat162float(h[jj]));
            }
            __nv_bfloat16* p = sb + (size_t)n * 256 + jh * 64 + tx * 4;
            ((__nv_bfloat162*)p)[0]         = __halves2bfloat162(h[0], h[1]);
            ((__nv_bfloat162*)p)[1]         = __halves2bfloat162(h[2], h[3]);
            ((__nv_bfloat162*)(p + 128))[0] = __halves2bfloat162(l[0], l[1]);
            ((__nv_bfloat162*)(p + 128))[1] = __halves2bfloat162(l[2], l[3]);
        }
    }
}

// -----------------------------------------------------------------------------
// Flash attention, tensor-core QK^T (bf16 split, 3 cross terms), 2-wide V.
// Block: 64 queries; 8 warps = 4 q-groups x 2 key-halves. 32-key tiles,
// cp.async double buffered. Per-warp online softmax, merged across key-halves.
// -----------------------------------------------------------------------------
__global__ __launch_bounds__(256, 2) void attn_kernel(
    const float* __restrict__ flow, float* __restrict__ out)
{
    __shared__ __align__(16) __nv_bfloat16 sK[2][KT][SROW];   // 33792 B; doubles as Q staging
    __shared__ float4 mbuf[64];

    const int b   = blockIdx.y;
    const int n0  = blockIdx.x * 64;
    const int tid = threadIdx.x;
    const int lane = tid & 31;
    const int warp = tid >> 5;
    const int qg = warp & 3;    // query group (16 rows)
    const int kh = warp >> 2;   // key half within each 32-key tile

    __nv_bfloat16* sQ = &sK[0][0][0];  // 64 rows x SROW during staging

    // stage Q tile: 64 rows x 256 bf16  (2048 uint4 chunks: 64 rows x 32)
    const __nv_bfloat16* Qg = g_Qs + ((size_t)b * NTOK + n0) * 256;
    #pragma unroll
    for (int i = 0; i < 8; i++) {
        int idx = tid + i * 256;
        int row = idx >> 5, c16 = idx & 31;
        *(uint4*)(sQ + row * SROW + c16 * 8) = *(const uint4*)(Qg + (size_t)row * 256 + c16 * 8);
    }
    __syncthreads();

    // A fragments for 16 ksteps (cols 0..255 = qh|ql), rows qg*16..+15, kept in regs
    const int arow  = qg * 16 + (lane & 7) + ((lane >> 3) & 1) * 8;
    const int acol8 = (lane >> 4) * 8;
    unsigned a[16][4];
    #pragma unroll
    for (int ks = 0; ks < 16; ks++) {
        unsigned addr = smem_u32(sQ + arow * SROW + ks * 16 + acol8);
        asm volatile("ldmatrix.sync.aligned.m8n8.x4.shared.b16 {%0,%1,%2,%3}, [%4];"
                     : "=r"(a[ks][0]), "=r"(a[ks][1]), "=r"(a[ks][2]), "=r"(a[ks][3])
                     : "r"(addr));
    }
    __syncthreads();   // done with Q staging; smem becomes K double buffer

    const __nv_bfloat16* Kg = g_Ks + (size_t)b * NTOK * 256;
    auto load_tile = [&](int kt, int buf) {
        #pragma unroll
        for (int i = 0; i < 4; i++) {
            int idx = tid + i * 256;          // 1024 chunks: 32 rows x 32 x 16B
            int row = idx >> 5, c16 = idx & 31;
            unsigned dst = smem_u32(&sK[buf][row][c16 * 8]);
            const void* src = Kg + ((size_t)kt * KT + row) * 256 + c16 * 8;
            asm volatile("cp.async.ca.shared.global [%0], [%1], 16;\n" :: "r"(dst), "l"(src));
        }
        asm volatile("cp.async.commit_group;\n");
    };

    const int brow  = kh * 16 + (lane >> 4) * 8 + (lane & 7);
    const int bcol8 = ((lane >> 3) & 1) * 8;

    load_tile(0, 0);

    float M[2]  = {-CUDART_INF_F, -CUDART_INF_F};
    float L[2]  = {0.f, 0.f};
    float P0[2] = {0.f, 0.f};
    float P1[2] = {0.f, 0.f};

    const float* V0 = flow + (size_t)b * 2 * NTOK;
    const float* V1 = V0 + NTOK;

    for (int kt = 0; kt < NKT; kt++) {
        asm volatile("cp.async.wait_group 0;\n" ::: "memory");
        __syncthreads();
        if (kt + 1 < NKT) load_tile(kt + 1, (kt + 1) & 1);

        const __nv_bfloat16* kb = &sK[kt & 1][0][0];

        float d0[4] = {0.f, 0.f, 0.f, 0.f};
        float d1[4] = {0.f, 0.f, 0.f, 0.f};
        // ksteps: 0-7 qh*kh, 8-15 ql*kh, 16-23 qh*kl
        #pragma unroll
        for (int ks = 0; ks < 24; ks++) {
            int bc = (ks & 7) * 16 + ((ks >> 4) & 1) * 128;
            unsigned addr = smem_u32(kb + brow * SROW + bc + bcol8);
            unsigned r0, r1, r2, r3;
            asm volatile("ldmatrix.sync.aligned.m8n8.x4.shared.b16 {%0,%1,%2,%3}, [%4];"
                         : "=r"(r0), "=r"(r1), "=r"(r2), "=r"(r3) : "r"(addr));
            const unsigned* af = a[ks & 15];
            mma16816(d0, af, r0, r1);
            mma16816(d1, af, r2, r3);
        }

        // V values for this thread's 4 key pairs
        int kb0 = kt * KT + kh * 16 + (lane & 3) * 2;
        float2 va0 = *(const float2*)(V0 + kb0);
        float2 va1 = *(const float2*)(V0 + kb0 + 8);
        float2 vb0 = *(const float2*)(V1 + kb0);
        float2 vb1 = *(const float2*)(V1 + kb0 + 8);

        // online softmax, rows r=0 (lane/4) and r=1 (lane/4+8)
        #pragma unroll
        for (int r = 0; r < 2; r++) {
            float s0 = r ? d0[2] : d0[0];
            float s1 = r ? d0[3] : d0[1];
            float s2 = r ? d1[2] : d1[0];
            float s3 = r ? d1[3] : d1[1];
            float mx = fmaxf(fmaxf(s0, s1), fmaxf(s2, s3));
            mx = fmaxf(mx, __shfl_xor_sync(0xffffffffu, mx, 1));
            mx = fmaxf(mx, __shfl_xor_sync(0xffffffffu, mx, 2));
            float nm = fmaxf(M[r], mx);
            float corr = __expf(M[r] - nm);
            float p0 = __expf(s0 - nm), p1 = __expf(s1 - nm);
            float p2 = __expf(s2 - nm), p3 = __expf(s3 - nm);
            float ps = (p0 + p1) + (p2 + p3);
            float q0 = p0 * va0.x + p1 * va0.y + p2 * va1.x + p3 * va1.y;
            float q1 = p0 * vb0.x + p1 * vb0.y + p2 * vb1.x + p3 * vb1.y;
            ps += __shfl_xor_sync(0xffffffffu, ps, 1);
            ps += __shfl_xor_sync(0xffffffffu, ps, 2);
            q0 += __shfl_xor_sync(0xffffffffu, q0, 1);
            q0 += __shfl_xor_sync(0xffffffffu, q0, 2);
            q1 += __shfl_xor_sync(0xffffffffu, q1, 1);
            q1 += __shfl_xor_sync(0xffffffffu, q1, 2);
            M[r]  = nm;
            L[r]  = L[r]  * corr + ps;
            P0[r] = P0[r] * corr + q0;
            P1[r] = P1[r] * corr + q1;
        }
    }

    // merge the two key-half partials
    __syncthreads();
    if (kh == 1 && (lane & 3) == 0) {
        #pragma unroll
        for (int r = 0; r < 2; r++) {
            int row = qg * 16 + (lane >> 2) + r * 8;
            mbuf[row] = make_float4(M[r], L[r], P0[r], P1[r]);
        }
    }
    __syncthreads();
    if (kh == 0 && (lane & 3) == 0) {
        #pragma unroll
        for (int r = 0; r < 2; r++) {
            int row = qg * 16 + (lane >> 2) + r * 8;
            float4 o = mbuf[row];
            float nm = fmaxf(M[r], o.x);
            float ca = __expf(M[r] - nm), cb = __expf(o.x - nm);
            float Lt = L[r] * ca + o.y * cb;
            float inv = 1.0f / Lt;
            int n = n0 + row;
            out[((size_t)b * 2 + 0) * NTOK + n] = (P0[r] * ca + o.z * cb) * inv;
            out[((size_t)b * 2 + 1) * NTOK + n] = (P1[r] * ca + o.w * cb) * inv;
        }
    }
}

extern "C" void kernel_launch(void* const* d_in, const int* in_sizes, int n_in,
                              void* d_out, int out_size)
{
    const float* feature0 = (const float*)d_in[0];
    const float* flow     = (const float*)d_in[1];
    const float* Wq       = (const float*)d_in[2];
    const float* bq       = (const float*)d_in[3];
    const float* Wk       = (const float*)d_in[4];
    const float* bk       = (const float*)d_in[5];
    float* out = (float*)d_out;

    float* qf = nullptr;
    __nv_bfloat16 *qs = nullptr, *ks = nullptr;
    cudaGetSymbolAddress((void**)&qf, g_Q);
    cudaGetSymbolAddress((void**)&qs, g_Qs);
    cudaGetSymbolAddress((void**)&ks, g_Ks);

    dim3 grid(NTOK / 64, BATCH);
    // Q = X Wq^T + bq ; split scaled by 1/sqrt(128)
    proj_kernel<<<grid, 256>>>(feature0, Wq, bq, qf, qs, 0.08838834764831845f);
    // K = Q Wk^T + bk ; split unscaled (fp32 copy not needed)
    proj_kernel<<<grid, 256>>>(qf, Wk, bk, nullptr, ks, 1.0f);
    attn_kernel<<<grid, 256>>>(flow, out);
}

// round 16
// speedup vs baseline: 1.0085x; 1.0085x over previous
#include <cuda_runtime.h>
#include <cuda_bf16.h>
#include <math_constants.h>

#define NTOK 4096
#define CDIM 128
#define BATCH 4
#define KT 32
#define NKT (NTOK / KT)
#define SROW 264   // smem row stride in bf16 elems (256 + 8 pad -> 528B, conflict-free ldmatrix)

// scratch
__device__ float g_Q[BATCH * CDIM * NTOK];                        // fp32 [b][c][n] (input to K proj)
__device__ __nv_bfloat16 g_Qs[(size_t)BATCH * NTOK * 256];        // [b][n][ qh(128) | ql(128) ], pre-scaled
__device__ __nv_bfloat16 g_Ks[(size_t)BATCH * NTOK * 256];        // [b][m][ kh(128) | kl(128) ]

__device__ __forceinline__ unsigned smem_u32(const void* p) {
    return (unsigned)__cvta_generic_to_shared(p);
}

__device__ __forceinline__ void mma16816(float* d, const unsigned* a, unsigned b0, unsigned b1) {
    asm volatile("mma.sync.aligned.m16n8k16.row.col.f32.bf16.bf16.f32 "
                 "{%0,%1,%2,%3}, {%4,%5,%6,%7}, {%8,%9}, {%0,%1,%2,%3};"
                 : "+f"(d[0]), "+f"(d[1]), "+f"(d[2]), "+f"(d[3])
                 : "r"(a[0]), "r"(a[1]), "r"(a[2]), "r"(a[3]), "r"(b0), "r"(b1));
}

// -----------------------------------------------------------------------------
// Projection: fin[b][c][n] = sum_k in[b][k][n] * W[c][k] + bias[c]
// Writes optional fp32 [b][c][n] and always the scaled bf16 hi/lo split [b][n][2c].
// grid (64, BATCH), 256 threads; per-thread tile: 8 c x 4 n.
// -----------------------------------------------------------------------------
__global__ __launch_bounds__(256) void proj_kernel(
    const float* __restrict__ in, const float* __restrict__ W,
    const float* __restrict__ bias, float* __restrict__ out_f32,
    __nv_bfloat16* __restrict__ out_split, float scale)
{
    __shared__ float Ins[32][64];
    __shared__ float Ws[32][132];

    const int b  = blockIdx.y;
    const int n0 = blockIdx.x * 64;
    const int tid = threadIdx.x;
    const int tx = tid & 15;
    const int ty = tid >> 4;

    const float* inb = in + (size_t)b * CDIM * NTOK;

    float acc[2][4][4];
    #pragma unroll
    for (int jh = 0; jh < 2; jh++)
        #pragma unroll
        for (int jj = 0; jj < 4; jj++)
            #pragma unroll
            for (int i = 0; i < 4; i++) acc[jh][jj][i] = 0.f;

    for (int k0 = 0; k0 < CDIM; k0 += 32) {
        #pragma unroll
        for (int r = 0; r < 2; r++) {
            int idx = tid + r * 256;
            int kk = idx >> 4;
            int nn = (idx & 15) << 2;
            float4 v = *(const float4*)(inb + (size_t)(k0 + kk) * NTOK + n0 + nn);
            *(float4*)(&Ins[kk][nn]) = v;
        }
        #pragma unroll
        for (int r = 0; r < 4; r++) {
            int idx = tid + r * 256;
            int c  = idx >> 3;
            int kk = (idx & 7) << 2;
            float4 v = *(const float4*)(W + (size_t)c * CDIM + k0 + kk);
            Ws[kk + 0][c] = v.x;
            Ws[kk + 1][c] = v.y;
            Ws[kk + 2][c] = v.z;
            Ws[kk + 3][c] = v.w;
        }
        __syncthreads();

        #pragma unroll
        for (int k = 0; k < 32; k++) {
            float4 q  = *(const float4*)(&Ins[k][ty * 4]);
            float4 w0 = *(const float4*)(&Ws[k][tx * 4]);
            float4 w1 = *(const float4*)(&Ws[k][64 + tx * 4]);
            float qv[4]  = {q.x, q.y, q.z, q.w};
            float w0v[4] = {w0.x, w0.y, w0.z, w0.w};
            float w1v[4] = {w1.x, w1.y, w1.z, w1.w};
            #pragma unroll
            for (int jj = 0; jj < 4; jj++)
                #pragma unroll
                for (int i = 0; i < 4; i++) {
                    acc[0][jj][i] = fmaf(w0v[jj], qv[i], acc[0][jj][i]);
                    acc[1][jj][i] = fmaf(w1v[jj], qv[i], acc[1][jj][i]);
                }
        }
        __syncthreads();
    }

    // add bias
    float fin[2][4][4];
    #pragma unroll
    for (int jh = 0; jh < 2; jh++)
        #pragma unroll
        for (int jj = 0; jj < 4; jj++) {
            float bv = bias[jh * 64 + tx * 4 + jj];
            #pragma unroll
            for (int i = 0; i < 4; i++) fin[jh][jj][i] = acc[jh][jj][i] + bv;
        }

    if (out_f32) {
        float* outb = out_f32 + (size_t)b * CDIM * NTOK;
        #pragma unroll
        for (int jh = 0; jh < 2; jh++)
            #pragma unroll
            for (int jj = 0; jj < 4; jj++) {
                int c = jh * 64 + tx * 4 + jj;
                float4 v = make_float4(fin[jh][jj][0], fin[jh][jj][1],
                                       fin[jh][jj][2], fin[jh][jj][3]);
                *(float4*)(outb + (size_t)c * NTOK + n0 + ty * 4) = v;
            }
    }

    // scaled bf16 hi/lo split, layout [b][n][ hi(0..127) | lo(128..255) ]
    __nv_bfloat16* sb = out_split + (size_t)b * NTOK * 256;
    #pragma unroll
    for (int i = 0; i < 4; i++) {
        int n = n0 + ty * 4 + i;
        #pragma unroll
        for (int jh = 0; jh < 2; jh++) {
            __nv_bfloat16 h[4], l[4];
            #pragma unroll
            for (int jj = 0; jj < 4; jj++) {
                float v = fin[jh][jj][i] * scale;
                h[jj] = __float2bfloat16(v);
                l[jj] = __float2bfloat16(v - __bfloat162float(h[jj]));
            }
            __nv_bfloat16* p = sb + (size_t)n * 256 + jh * 64 + tx * 4;
            ((__nv_bfloat162*)p)[0]         = __halves2bfloat162(h[0], h[1]);
            ((__nv_bfloat162*)p)[1]         = __halves2bfloat162(h[2], h[3]);
            ((__nv_bfloat162*)(p + 128))[0] = __halves2bfloat162(l[0], l[1]);
            ((__nv_bfloat162*)(p + 128))[1] = __halves2bfloat162(l[2], l[3]);
        }
    }
}

// -----------------------------------------------------------------------------
// Flash attention, tensor-core QK^T (bf16 split, 3 cross terms), 2-wide V.
// Block: 64 queries; 8 warps = 4 q-groups x 2 key-halves. 32-key tiles,
// cp.async double buffered. Per-warp online softmax, merged across key-halves.
// -----------------------------------------------------------------------------
__global__ __launch_bounds__(256, 2) void attn_kernel(
    const float* __restrict__ flow, float* __restrict__ out)
{
    __shared__ __align__(16) __nv_bfloat16 sK[2][KT][SROW];   // 33792 B; doubles as Q staging
    __shared__ float4 mbuf[64];

    const int b   = blockIdx.y;
    const int n0  = blockIdx.x * 64;
    const int tid = threadIdx.x;
    const int lane = tid & 31;
    const int warp = tid >> 5;
    const int qg = warp & 3;    // query group (16 rows)
    const int kh = warp >> 2;   // key half within each 32-key tile

    __nv_bfloat16* sQ = &sK[0][0][0];  // 64 rows x SROW during staging

    // stage Q tile: 64 rows x 256 bf16  (2048 uint4 chunks: 64 rows x 32)
    const __nv_bfloat16* Qg = g_Qs + ((size_t)b * NTOK + n0) * 256;
    #pragma unroll
    for (int i = 0; i < 8; i++) {
        int idx = tid + i * 256;
        int row = idx >> 5, c16 = idx & 31;
        *(uint4*)(sQ + row * SROW + c16 * 8) = *(const uint4*)(Qg + (size_t)row * 256 + c16 * 8);
    }
    __syncthreads();

    // A fragments for 16 ksteps (cols 0..255 = qh|ql), rows qg*16..+15, kept in regs
    const int arow  = qg * 16 + (lane & 7) + ((lane >> 3) & 1) * 8;
    const int acol8 = (lane >> 4) * 8;
    unsigned a[16][4];
    #pragma unroll
    for (int ks = 0; ks < 16; ks++) {
        unsigned addr = smem_u32(sQ + arow * SROW + ks * 16 + acol8);
        asm volatile("ldmatrix.sync.aligned.m8n8.x4.shared.b16 {%0,%1,%2,%3}, [%4];"
                     : "=r"(a[ks][0]), "=r"(a[ks][1]), "=r"(a[ks][2]), "=r"(a[ks][3])
                     : "r"(addr));
    }
    __syncthreads();   // done with Q staging; smem becomes K double buffer

    const __nv_bfloat16* Kg = g_Ks + (size_t)b * NTOK * 256;
    auto load_tile = [&](int kt, int buf) {
        #pragma unroll
        for (int i = 0; i < 4; i++) {
            int idx = tid + i * 256;          // 1024 chunks: 32 rows x 32 x 16B
            int row = idx >> 5, c16 = idx & 31;
            unsigned dst = smem_u32(&sK[buf][row][c16 * 8]);
            const void* src = Kg + ((size_t)kt * KT + row) * 256 + c16 * 8;
            asm volatile("cp.async.ca.shared.global [%0], [%1], 16;\n" :: "r"(dst), "l"(src));
        }
        asm volatile("cp.async.commit_group;\n");
    };

    const int brow  = kh * 16 + (lane >> 4) * 8 + (lane & 7);
    const int bcol8 = ((lane >> 3) & 1) * 8;

    load_tile(0, 0);

    float M[2]  = {-CUDART_INF_F, -CUDART_INF_F};
    float L[2]  = {0.f, 0.f};
    float P0[2] = {0.f, 0.f};
    float P1[2] = {0.f, 0.f};

    const float* V0 = flow + (size_t)b * 2 * NTOK;
    const float* V1 = V0 + NTOK;

    for (int kt = 0; kt < NKT; kt++) {
        asm volatile("cp.async.wait_group 0;\n" ::: "memory");
        __syncthreads();
        if (kt + 1 < NKT) load_tile(kt + 1, (kt + 1) & 1);

        const __nv_bfloat16* kb = &sK[kt & 1][0][0];

        float d0[4] = {0.f, 0.f, 0.f, 0.f};
        float d1[4] = {0.f, 0.f, 0.f, 0.f};
        // ksteps: 0-7 qh*kh, 8-15 ql*kh, 16-23 qh*kl
        #pragma unroll
        for (int ks = 0; ks < 24; ks++) {
            int bc = (ks & 7) * 16 + ((ks >> 4) & 1) * 128;
            unsigned addr = smem_u32(kb + brow * SROW + bc + bcol8);
            unsigned r0, r1, r2, r3;
            asm volatile("ldmatrix.sync.aligned.m8n8.x4.shared.b16 {%0,%1,%2,%3}, [%4];"
                         : "=r"(r0), "=r"(r1), "=r"(r2), "=r"(r3) : "r"(addr));
            const unsigned* af = a[ks & 15];
            mma16816(d0, af, r0, r1);
            mma16816(d1, af, r2, r3);
        }

        // V values for this thread's 4 key pairs
        int kb0 = kt * KT + kh * 16 + (lane & 3) * 2;
        float2 va0 = *(const float2*)(V0 + kb0);
        float2 va1 = *(const float2*)(V0 + kb0 + 8);
        float2 vb0 = *(const float2*)(V1 + kb0);
        float2 vb1 = *(const float2*)(V1 + kb0 + 8);

        // online softmax, rows r=0 (lane/4) and r=1 (lane/4+8)
        #pragma unroll
        for (int r = 0; r < 2; r++) {
            float s0 = r ? d0[2] : d0[0];
            float s1 = r ? d0[3] : d0[1];
            float s2 = r ? d1[2] : d1[0];
            float s3 = r ? d1[3] : d1[1];
            float mx = fmaxf(fmaxf(s0, s1), fmaxf(s2, s3));
            mx = fmaxf(mx, __shfl_xor_sync(0xffffffffu, mx, 1));
            mx = fmaxf(mx, __shfl_xor_sync(0xffffffffu, mx, 2));
            float nm = fmaxf(M[r], mx);
            float corr = __expf(M[r] - nm);
            float p0 = __expf(s0 - nm), p1 = __expf(s1 - nm);
            float p2 = __expf(s2 - nm), p3 = __expf(s3 - nm);
            float ps = (p0 + p1) + (p2 + p3);
            float q0 = p0 * va0.x + p1 * va0.y + p2 * va1.x + p3 * va1.y;
            float q1 = p0 * vb0.x + p1 * vb0.y + p2 * vb1.x + p3 * vb1.y;
            ps += __shfl_xor_sync(0xffffffffu, ps, 1);
            ps += __shfl_xor_sync(0xffffffffu, ps, 2);
            q0 += __shfl_xor_sync(0xffffffffu, q0, 1);
            q0 += __shfl_xor_sync(0xffffffffu, q0, 2);
            q1 += __shfl_xor_sync(0xffffffffu, q1, 1);
            q1 += __shfl_xor_sync(0xffffffffu, q1, 2);
            M[r]  = nm;
            L[r]  = L[r]  * corr + ps;
            P0[r] = P0[r] * corr + q0;
            P1[r] = P1[r] * corr + q1;
        }
    }

    // merge the two key-half partials
    __syncthreads();
    if (kh == 1 && (lane & 3) == 0) {
        #pragma unroll
        for (int r = 0; r < 2; r++) {
            int row = qg * 16 + (lane >> 2) + r * 8;
            mbuf[row] = make_float4(M[r], L[r], P0[r], P1[r]);
        }
    }
    __syncthreads();
    if (kh == 0 && (lane & 3) == 0) {
        #pragma unroll
        for (int r = 0; r < 2; r++) {
            int row = qg * 16 + (lane >> 2) + r * 8;
            float4 o = mbuf[row];
            float nm = fmaxf(M[r], o.x);
            float ca = __expf(M[r] - nm), cb = __expf(o.x - nm);
            float Lt = L[r] * ca + o.y * cb;
            float inv = 1.0f / Lt;
            int n = n0 + row;
            out[((size_t)b * 2 + 0) * NTOK + n] = (P0[r] * ca + o.z * cb) * inv;
            out[((size_t)b * 2 + 1) * NTOK + n] = (P1[r] * ca + o.w * cb) * inv;
        }
    }
}

extern "C" void kernel_launch(void* const* d_in, const int* in_sizes, int n_in,
                              void* d_out, int out_size)
{
    const float* feature0 = (const float*)d_in[0];
    const float* flow     = (const float*)d_in[1];
    const float* Wq       = (const float*)d_in[2];
    const float* bq       = (const float*)d_in[3];
    const float* Wk       = (const float*)d_in[4];
    const float* bk       = (const float*)d_in[5];
    float* out = (float*)d_out;

    float* qf = nullptr;
    __nv_bfloat16 *qs = nullptr, *ks = nullptr;
    cudaGetSymbolAddress((void**)&qf, g_Q);
    cudaGetSymbolAddress((void**)&qs, g_Qs);
    cudaGetSymbolAddress((void**)&ks, g_Ks);

    dim3 grid(NTOK / 64, BATCH);
    // Q = X Wq^T + bq ; split scaled by 1/sqrt(128)
    proj_kernel<<<grid, 256>>>(feature0, Wq, bq, qf, qs, 0.08838834764831845f);
    // K = Q Wk^T + bk ; split unscaled (fp32 copy not needed)
    proj_kernel<<<grid, 256>>>(qf, Wk, bk, nullptr, ks, 1.0f);
    attn_kernel<<<grid, 256>>>(flow, out);
}